// round 12
// baseline (speedup 1.0000x reference)
#include <cuda_runtime.h>
#include <cstdint>

#define NN   50000
#define TT   128
#define INF  6
#define HH   32
#define NE   2000
#define NI   150000
#define RRF  16

typedef unsigned long long u64;

// ---------------- scratch (device globals, no allocation) ----------------
__device__ float g_A  [NN * HH];
__device__ float g_XW [NN * HH];
__device__ float g_AGG[NN * HH];
__device__ float g_EF [NE * HH];
__device__ float g_degB[NE];
__device__ float g_degD[NN];
__device__ float g_XT [(size_t)TT * INF * NN];  // [t][f][node]

// ---------------- helpers ----------------
__device__ __forceinline__ u64 ffma2(u64 a, u64 b, u64 c) {
    u64 d;
    asm("fma.rn.f32x2 %0, %1, %2, %3;" : "=l"(d) : "l"(a), "l"(b), "l"(c));
    return d;
}
__device__ __forceinline__ u64 pk2(float lo, float hi) {
    u64 r;
    asm("mov.b64 %0, {%1, %2};" : "=l"(r) : "f"(lo), "f"(hi));
    return r;
}
__device__ __forceinline__ float2 up2(u64 v) {
    float2 f;
    asm("mov.b64 {%0, %1}, %2;" : "=f"(f.x), "=f"(f.y) : "l"(v));
    return f;
}
// single-MUFU activations (sm_75+ tanh.approx: ~1e-5 rel err, 16 cyc)
__device__ __forceinline__ float tanh_fast(float x) {
    float t;
    asm("tanh.approx.f32 %0, %1;" : "=f"(t) : "f"(x));
    return t;
}
__device__ __forceinline__ float sigm(float x) {
    float t;
    asm("tanh.approx.f32 %0, %1;" : "=f"(t) : "f"(0.5f * x));
    return fmaf(t, 0.5f, 0.5f);
}

// ---------------- transpose price [n][t][f] -> [t][f][n] ----------------
__global__ void __launch_bounds__(256) transpose_kernel(const float* __restrict__ x) {
    __shared__ float s[64 * 97];
    const int n0 = blockIdx.x * 64;
    const int t0 = blockIdx.y * 16;
    for (int i = threadIdx.x; i < 64 * 96; i += 256) {
        int n = i / 96, j = i % 96;
        int nc = n0 + n < NN ? n0 + n : NN - 1;
        s[n * 97 + j] = x[(size_t)nc * (TT * INF) + t0 * INF + j];
    }
    __syncthreads();
    for (int i = threadIdx.x; i < 64 * 96; i += 256) {
        int row = i >> 6, n = i & 63;
        if (n0 + n < NN)
            g_XT[((size_t)t0 * INF + row) * NN + n0 + n] = s[n * 97 + row];
    }
}

// ---------------- GRU kernel ----------------
// TWO nodes per thread: every broadcast weight load feeds 4 FFMA2 (2 outputs
// x 2 nodes) instead of 2 — halves the L1/smem return traffic per node,
// which round-11 ncu showed to be the binding resource (L1=69%).
// 32-thread blocks, 782 blocks, launch_bounds(32,8): reg cap 256.
// Gates fully sequential (R -> N -> Z) so only two 16xu64 acc sets are live.
struct __align__(16) SmemGRU {
    u64 wr[32 * 16], wz[32 * 16], wn[32 * 16];  // W_hh pairs [k][jp]
    u64 uir[6 * 16], uiz[6 * 16], uin[6 * 16];  // W_ih pairs [f][jp]
    u64 br[16], bz[16], bhn[16], bin[16];
};

__global__ void __launch_bounds__(32, 8) gru_kernel(
    const float* __restrict__ W_ih, const float* __restrict__ W_hh,
    const float* __restrict__ b_ih, const float* __restrict__ b_hh)
{
    __shared__ SmemGRU sm;
    const int tid = threadIdx.x;

    for (int idx = tid; idx < 512; idx += 32) {
        int k = idx >> 4, jp = idx & 15;
        sm.wr[idx] = pk2(W_hh[(     2 * jp) * HH + k], W_hh[(     2 * jp + 1) * HH + k]);
        sm.wz[idx] = pk2(W_hh[(32 + 2 * jp) * HH + k], W_hh[(32 + 2 * jp + 1) * HH + k]);
        sm.wn[idx] = pk2(W_hh[(64 + 2 * jp) * HH + k], W_hh[(64 + 2 * jp + 1) * HH + k]);
    }
    for (int idx = tid; idx < 96; idx += 32) {
        int f = idx >> 4, jp = idx & 15;
        sm.uir[idx] = pk2(W_ih[(     2 * jp) * INF + f], W_ih[(     2 * jp + 1) * INF + f]);
        sm.uiz[idx] = pk2(W_ih[(32 + 2 * jp) * INF + f], W_ih[(32 + 2 * jp + 1) * INF + f]);
        sm.uin[idx] = pk2(W_ih[(64 + 2 * jp) * INF + f], W_ih[(64 + 2 * jp + 1) * INF + f]);
    }
    if (tid < 16) {
        int jp = tid;
        sm.br [jp] = pk2(b_ih[2 * jp] + b_hh[2 * jp],
                         b_ih[2 * jp + 1] + b_hh[2 * jp + 1]);
        sm.bz [jp] = pk2(b_ih[32 + 2 * jp] + b_hh[32 + 2 * jp],
                         b_ih[32 + 2 * jp + 1] + b_hh[32 + 2 * jp + 1]);
        sm.bhn[jp] = pk2(b_hh[64 + 2 * jp], b_hh[64 + 2 * jp + 1]);
        sm.bin[jp] = pk2(b_ih[64 + 2 * jp], b_ih[64 + 2 * jp + 1]);
    }
    __syncthreads();

    // node a = block*64 + tid, node b = a + 32 (both warps' loads coalesced)
    const int nodeA = blockIdx.x * 64 + tid;
    const int nodeB = nodeA + 32;
    const int ncA = nodeA < NN ? nodeA : NN - 1;
    const int ncB = nodeB < NN ? nodeB : NN - 1;

    float hA[32], hB[32];
#pragma unroll
    for (int i = 0; i < 32; i++) { hA[i] = 0.f; hB[i] = 0.f; }

    u64 accA[16], accB[16];   // gate accumulator: R pass, then Z pass
    u64 nAcc[16], nBcc[16];   // N accumulator, then packed n

    for (int t = 0; t < TT; t++) {
        float xa[6], xb[6];
#pragma unroll
        for (int f = 0; f < 6; f++) {
            const float* p = &g_XT[((size_t)t * INF + f) * NN];
            xa[f] = p[ncA];
            xb[f] = p[ncB];
        }

        // ---- R pass: acc = br + Whh_r h + Uir x ; r = sigm ----
#pragma unroll
        for (int jp = 0; jp < 16; jp++) { accA[jp] = sm.br[jp]; accB[jp] = sm.br[jp]; }
#pragma unroll 8
        for (int k = 0; k < 32; k++) {
            u64 ha = pk2(hA[k], hA[k]);
            u64 hb = pk2(hB[k], hB[k]);
            const ulonglong2* p = reinterpret_cast<const ulonglong2*>(&sm.wr[k * 16]);
#pragma unroll
            for (int j2 = 0; j2 < 8; j2++) {
                ulonglong2 w = p[j2];
                accA[2 * j2]     = ffma2(w.x, ha, accA[2 * j2]);
                accA[2 * j2 + 1] = ffma2(w.y, ha, accA[2 * j2 + 1]);
                accB[2 * j2]     = ffma2(w.x, hb, accB[2 * j2]);
                accB[2 * j2 + 1] = ffma2(w.y, hb, accB[2 * j2 + 1]);
            }
        }
#pragma unroll
        for (int f = 0; f < 6; f++) {
            u64 xda = pk2(xa[f], xa[f]);
            u64 xdb = pk2(xb[f], xb[f]);
#pragma unroll
            for (int jp = 0; jp < 16; jp++) {
                u64 w = sm.uir[f * 16 + jp];
                accA[jp] = ffma2(w, xda, accA[jp]);
                accB[jp] = ffma2(w, xdb, accB[jp]);
            }
        }
#pragma unroll
        for (int jp = 0; jp < 16; jp++) {
            float2 a = up2(accA[jp]);
            accA[jp] = pk2(sigm(a.x), sigm(a.y));
            float2 b = up2(accB[jp]);
            accB[jp] = pk2(sigm(b.x), sigm(b.y));
        }

        // ---- N pass: nAcc = bhn + Whh_n h ----
#pragma unroll
        for (int jp = 0; jp < 16; jp++) { nAcc[jp] = sm.bhn[jp]; nBcc[jp] = sm.bhn[jp]; }
#pragma unroll 8
        for (int k = 0; k < 32; k++) {
            u64 ha = pk2(hA[k], hA[k]);
            u64 hb = pk2(hB[k], hB[k]);
            const ulonglong2* p = reinterpret_cast<const ulonglong2*>(&sm.wn[k * 16]);
#pragma unroll
            for (int j2 = 0; j2 < 8; j2++) {
                ulonglong2 w = p[j2];
                nAcc[2 * j2]     = ffma2(w.x, ha, nAcc[2 * j2]);
                nAcc[2 * j2 + 1] = ffma2(w.y, ha, nAcc[2 * j2 + 1]);
                nBcc[2 * j2]     = ffma2(w.x, hb, nBcc[2 * j2]);
                nBcc[2 * j2 + 1] = ffma2(w.y, hb, nBcc[2 * j2 + 1]);
            }
        }
        // n = tanh( bin + Uin x + r * nAcc )   (consumes r -> acc regs free)
#pragma unroll
        for (int jp = 0; jp < 16; jp++) {
            nAcc[jp] = ffma2(accA[jp], nAcc[jp], sm.bin[jp]);
            nBcc[jp] = ffma2(accB[jp], nBcc[jp], sm.bin[jp]);
        }
#pragma unroll
        for (int f = 0; f < 6; f++) {
            u64 xda = pk2(xa[f], xa[f]);
            u64 xdb = pk2(xb[f], xb[f]);
#pragma unroll
            for (int jp = 0; jp < 16; jp++) {
                u64 w = sm.uin[f * 16 + jp];
                nAcc[jp] = ffma2(w, xda, nAcc[jp]);
                nBcc[jp] = ffma2(w, xdb, nBcc[jp]);
            }
        }
#pragma unroll
        for (int jp = 0; jp < 16; jp++) {
            float2 a = up2(nAcc[jp]);
            nAcc[jp] = pk2(tanh_fast(a.x), tanh_fast(a.y));
            float2 b = up2(nBcc[jp]);
            nBcc[jp] = pk2(tanh_fast(b.x), tanh_fast(b.y));
        }

        // ---- Z pass (reuses acc regs): acc = bz + Whh_z h + Uiz x ----
#pragma unroll
        for (int jp = 0; jp < 16; jp++) { accA[jp] = sm.bz[jp]; accB[jp] = sm.bz[jp]; }
#pragma unroll 8
        for (int k = 0; k < 32; k++) {
            u64 ha = pk2(hA[k], hA[k]);
            u64 hb = pk2(hB[k], hB[k]);
            const ulonglong2* p = reinterpret_cast<const ulonglong2*>(&sm.wz[k * 16]);
#pragma unroll
            for (int j2 = 0; j2 < 8; j2++) {
                ulonglong2 w = p[j2];
                accA[2 * j2]     = ffma2(w.x, ha, accA[2 * j2]);
                accA[2 * j2 + 1] = ffma2(w.y, ha, accA[2 * j2 + 1]);
                accB[2 * j2]     = ffma2(w.x, hb, accB[2 * j2]);
                accB[2 * j2 + 1] = ffma2(w.y, hb, accB[2 * j2 + 1]);
            }
        }
#pragma unroll
        for (int f = 0; f < 6; f++) {
            u64 xda = pk2(xa[f], xa[f]);
            u64 xdb = pk2(xb[f], xb[f]);
#pragma unroll
            for (int jp = 0; jp < 16; jp++) {
                u64 w = sm.uiz[f * 16 + jp];
                accA[jp] = ffma2(w, xda, accA[jp]);
                accB[jp] = ffma2(w, xdb, accB[jp]);
            }
        }

        // ---- h' = n + sigm(z)*(h - n) ----
#pragma unroll
        for (int jp = 0; jp < 16; jp++) {
            float2 za = up2(accA[jp]);
            float2 na = up2(nAcc[jp]);
            float z0 = sigm(za.x), z1 = sigm(za.y);
            hA[2 * jp]     = na.x + z0 * (hA[2 * jp]     - na.x);
            hA[2 * jp + 1] = na.y + z1 * (hA[2 * jp + 1] - na.y);
            float2 zb = up2(accB[jp]);
            float2 nb = up2(nBcc[jp]);
            float y0 = sigm(zb.x), y1 = sigm(zb.y);
            hB[2 * jp]     = nb.x + y0 * (hB[2 * jp]     - nb.x);
            hB[2 * jp + 1] = nb.y + y1 * (hB[2 * jp + 1] - nb.y);
        }
    }

    if (nodeA < NN) {
#pragma unroll
        for (int c = 0; c < 32; c++) {
            float v = hA[c];
            g_A[(size_t)nodeA * 32 + c] = v > 0.f ? v : 0.01f * v;
        }
    }
    if (nodeB < NN) {
#pragma unroll
        for (int c = 0; c < 32; c++) {
            float v = hB[c];
            g_A[(size_t)nodeB * 32 + c] = v > 0.f ? v : 0.01f * v;
        }
    }
}

// ---------------- hypergraph kernels ----------------
__device__ __forceinline__ void red_add_v2(float* p, float a, float b) {
    asm volatile("red.global.add.v2.f32 [%0], {%1, %2};"
                 :: "l"(p), "f"(a), "f"(b) : "memory");
}
__global__ void zero_deg_kernel() {
    int i = blockIdx.x * blockDim.x + threadIdx.x;
    if (i < NE) g_degB[i] = 0.f;
    if (i < NN) g_degD[i] = 0.f;
}
__global__ void count_deg_kernel(const int* __restrict__ nidx, const int* __restrict__ eidx) {
    int i = blockIdx.x * blockDim.x + threadIdx.x;
    if (i < NI) {
        atomicAdd(&g_degB[eidx[i]], 1.f);
        atomicAdd(&g_degD[nidx[i]], 1.f);
    }
}
__global__ void invert_deg_kernel() {
    int i = blockIdx.x * blockDim.x + threadIdx.x;
    if (i < NE) { float v = g_degB[i]; g_degB[i] = v > 0.f ? 1.f / v : 0.f; }
    if (i < NN) { float v = g_degD[i]; g_degD[i] = v > 0.f ? 1.f / v : 0.f; }
}
__global__ void zero_ef_agg_kernel() {
    int i = blockIdx.x * blockDim.x + threadIdx.x;
    if (i < NE * HH) g_EF[i] = 0.f;
    if (i < NN * HH) g_AGG[i] = 0.f;
}
__global__ void scatter_edge_kernel(const int* __restrict__ nidx, const int* __restrict__ eidx) {
    int idx = blockIdx.x * blockDim.x + threadIdx.x;
    if (idx < NI * 16) {
        int i = idx >> 4, c = (idx & 15) * 2;
        const float2 v = *reinterpret_cast<const float2*>(&g_XW[(size_t)nidx[i] * HH + c]);
        red_add_v2(&g_EF[eidx[i] * HH + c], v.x, v.y);
    }
}
__global__ void scatter_node_kernel(const int* __restrict__ nidx, const int* __restrict__ eidx) {
    int idx = blockIdx.x * blockDim.x + threadIdx.x;
    if (idx < NI * 16) {
        int i = idx >> 4, c = (idx & 15) * 2;
        int e = eidx[i];
        float s = g_degB[e];
        const float2 v = *reinterpret_cast<const float2*>(&g_EF[e * HH + c]);
        red_add_v2(&g_AGG[(size_t)nidx[i] * HH + c], v.x * s, v.y * s);
    }
}
__global__ void finalize_kernel(const float* __restrict__ bias) {
    int idx = blockIdx.x * blockDim.x + threadIdx.x;
    if (idx < NN * HH) {
        int n = idx >> 5, c = idx & 31;
        float v = g_AGG[idx] * g_degD[n] + bias[c];
        g_A[idx] = v > 0.f ? v : 0.2f * v;
    }
}
__global__ void dense_kernel(const float* __restrict__ W, const float* __restrict__ bias,
                             float* __restrict__ extout,
                             int nout, int hasBias, int hasAct, float slope) {
    __shared__ float sW[32 * 32];
    for (int i = threadIdx.x; i < nout * 32; i += blockDim.x) sW[i] = W[i];
    __syncthreads();
    int n = blockIdx.x * blockDim.x + threadIdx.x;
    if (n >= NN) return;
    float xin[32];
#pragma unroll
    for (int k = 0; k < 32; k++) xin[k] = g_A[(size_t)n * 32 + k];
    float* o = extout ? extout : g_XW;
    for (int j = 0; j < nout; j++) {
        float acc = hasBias ? bias[j] : 0.f;
#pragma unroll
        for (int k = 0; k < 32; k++) acc = fmaf(xin[k], sW[j * 32 + k], acc);
        if (hasAct) acc = acc > 0.f ? acc : slope * acc;
        o[(size_t)n * nout + j] = acc;
    }
}

// ---------------- launch ----------------
// gru_kernel stays the 4th launch (profiler pins launch #4).
extern "C" void kernel_launch(void* const* d_in, const int* in_sizes, int n_in,
                              void* d_out, int out_size) {
    const float* price = (const float*)d_in[0];
    const float* W_ih = (const float*)d_in[2];
    const float* W_hh = (const float*)d_in[3];
    const float* b_ih = (const float*)d_in[4];
    const float* b_hh = (const float*)d_in[5];
    const float* W1   = (const float*)d_in[6];
    const float* b1   = (const float*)d_in[7];
    const float* W2   = (const float*)d_in[8];
    const float* b2   = (const float*)d_in[9];
    const float* Wl   = (const float*)d_in[10];
    const float* bl   = (const float*)d_in[11];
    const int*   nidx = (const int*)d_in[12];
    const int*   eidx = (const int*)d_in[13];
    float* out = (float*)d_out;

    const int B256 = 256;
    transpose_kernel<<<dim3((NN + 63) / 64, TT / 16), 256>>>(price);      // 1
    zero_deg_kernel<<<(NN + B256 - 1) / B256, B256>>>();                  // 2
    count_deg_kernel<<<(NI + B256 - 1) / B256, B256>>>(nidx, eidx);       // 3
    gru_kernel<<<(NN + 63) / 64, 32>>>(W_ih, W_hh, b_ih, b_hh);           // 4 <- profiled
    invert_deg_kernel<<<(NN + B256 - 1) / B256, B256>>>();                // 5

    // conv1
    dense_kernel<<<(NN + 127) / 128, 128>>>(W1, nullptr, nullptr, 32, 0, 0, 0.f);
    zero_ef_agg_kernel<<<(NN * HH + B256 - 1) / B256, B256>>>();
    scatter_edge_kernel<<<(NI * 16 + B256 - 1) / B256, B256>>>(nidx, eidx);
    scatter_node_kernel<<<(NI * 16 + B256 - 1) / B256, B256>>>(nidx, eidx);
    finalize_kernel<<<(NN * HH + B256 - 1) / B256, B256>>>(b1);

    // conv2
    dense_kernel<<<(NN + 127) / 128, 128>>>(W2, nullptr, nullptr, 32, 0, 0, 0.f);
    zero_ef_agg_kernel<<<(NN * HH + B256 - 1) / B256, B256>>>();
    scatter_edge_kernel<<<(NI * 16 + B256 - 1) / B256, B256>>>(nidx, eidx);
    scatter_node_kernel<<<(NI * 16 + B256 - 1) / B256, B256>>>(nidx, eidx);
    finalize_kernel<<<(NN * HH + B256 - 1) / B256, B256>>>(b2);

    dense_kernel<<<(NN + 127) / 128, 128>>>(Wl, bl, out, RRF, 1, 1, 0.01f);
}

// round 13
// speedup vs baseline: 1.5908x; 1.5908x over previous
#include <cuda_runtime.h>
#include <cstdint>

#define NN   50000
#define TT   128
#define INF  6
#define HH   32
#define NE   2000
#define NI   150000
#define RRF  16

typedef unsigned long long u64;

// ---------------- scratch (device globals, no allocation) ----------------
__device__ float g_A  [NN * HH];
__device__ float g_XW [NN * HH];
__device__ float g_AGG[NN * HH];
__device__ float g_EF [NE * HH];
__device__ float g_degB[NE];
__device__ float g_degD[NN];

// ---------------- helpers ----------------
__device__ __forceinline__ u64 ffma2(u64 a, u64 b, u64 c) {
    u64 d;
    asm("fma.rn.f32x2 %0, %1, %2, %3;" : "=l"(d) : "l"(a), "l"(b), "l"(c));
    return d;
}
__device__ __forceinline__ u64 pk2(float lo, float hi) {
    u64 r;
    asm("mov.b64 %0, {%1, %2};" : "=l"(r) : "f"(lo), "f"(hi));
    return r;
}
__device__ __forceinline__ float2 up2(u64 v) {
    float2 f;
    asm("mov.b64 {%0, %1}, %2;" : "=f"(f.x), "=f"(f.y) : "l"(v));
    return f;
}
// single-MUFU activations (tanh.approx: measured rel_err impact ~1e-7 level)
__device__ __forceinline__ float tanh_fast(float x) {
    float t;
    asm("tanh.approx.f32 %0, %1;" : "=f"(t) : "f"(x));
    return t;
}
__device__ __forceinline__ float sigm(float x) {
    float t;
    asm("tanh.approx.f32 %0, %1;" : "=f"(t) : "f"(0.5f * x));
    return fmaf(t, 0.5f, 0.5f);
}

// ---------------- GRU: warp-cooperative GEMV ----------------
// Lane j permanently holds weight rows j / 32+j / 64+j (r,z,n) in REGISTERS
// (K-paired u64 for FFMA2). Per step, only h moves: 32 floats broadcast by
// shfl. Zero smem-crossbar traffic (round-12 ncu showed the crossbar was the
// binding resource: each thread privately re-received 14.4KB of weights per
// step). Warp processes 2 nodes; grid-stride over 25000 pairs so the weight
// load amortizes over ~16 pairs x 128 steps.
__global__ void __launch_bounds__(32, 11) gru_warp_kernel(
    const float* __restrict__ x,   // [NN][TT][INF]
    const float* __restrict__ W_ih, const float* __restrict__ W_hh,
    const float* __restrict__ b_ih, const float* __restrict__ b_hh)
{
    const int j = threadIdx.x;     // lane = output index

    // ---- persistent per-lane weights ----
    u64 wr2[16], wz2[16], wn2[16];
#pragma unroll
    for (int k2 = 0; k2 < 16; k2++) {
        wr2[k2] = pk2(W_hh[      j * HH + 2 * k2], W_hh[      j * HH + 2 * k2 + 1]);
        wz2[k2] = pk2(W_hh[(32 + j) * HH + 2 * k2], W_hh[(32 + j) * HH + 2 * k2 + 1]);
        wn2[k2] = pk2(W_hh[(64 + j) * HH + 2 * k2], W_hh[(64 + j) * HH + 2 * k2 + 1]);
    }
    float ur[6], uz[6], un[6];
#pragma unroll
    for (int f = 0; f < 6; f++) {
        ur[f] = W_ih[      j * INF + f];
        uz[f] = W_ih[(32 + j) * INF + f];
        un[f] = W_ih[(64 + j) * INF + f];
    }
    const float brj  = b_ih[j]      + b_hh[j];
    const float bzj  = b_ih[32 + j] + b_hh[32 + j];
    const float bhnj = b_hh[64 + j];
    const float binj = b_ih[64 + j];

    const unsigned FULL = 0xffffffffu;
    const int srcg = 2 * (j & 15);          // pair-gather source base

    for (int pair = blockIdx.x; pair < NN / 2; pair += gridDim.x) {
        const int nodeA = pair * 2;
        const int nodeB = nodeA + 1;
        const float* xA = x + (size_t)nodeA * (TT * INF);
        const float* xB = x + (size_t)nodeB * (TT * INF);

        float hAj = 0.f, hBj = 0.f;         // own output, prev step
        float hp0 = 0.f, hp1 = 0.f;         // packed pairs: lanes 0-15 hold A, 16-31 hold B

        for (int t = 0; t < TT; t++) {
            // uniform x loads (8B-aligned: offsets are multiples of 24B)
            float2 a01 = *(const float2*)(xA + t * 6);
            float2 a23 = *(const float2*)(xA + t * 6 + 2);
            float2 a45 = *(const float2*)(xA + t * 6 + 4);
            float2 b01 = *(const float2*)(xB + t * 6);
            float2 b23 = *(const float2*)(xB + t * 6 + 2);
            float2 b45 = *(const float2*)(xB + t * 6 + 4);
            float xa[6] = {a01.x, a01.y, a23.x, a23.y, a45.x, a45.y};
            float xb[6] = {b01.x, b01.y, b23.x, b23.y, b45.x, b45.y};

            // ---- hh dot products: h broadcast via shfl, weights in regs ----
            u64 aR = 0, aZ = 0, aN = 0, bR = 0, bZ = 0, bN = 0;
#pragma unroll
            for (int k2 = 0; k2 < 16; k2++) {
                u64 hA2 = pk2(__shfl_sync(FULL, hp0, k2),
                              __shfl_sync(FULL, hp1, k2));
                u64 hB2 = pk2(__shfl_sync(FULL, hp0, 16 + k2),
                              __shfl_sync(FULL, hp1, 16 + k2));
                aR = ffma2(wr2[k2], hA2, aR);
                bR = ffma2(wr2[k2], hB2, bR);
                aZ = ffma2(wz2[k2], hA2, aZ);
                bZ = ffma2(wz2[k2], hB2, bZ);
                aN = ffma2(wn2[k2], hA2, aN);
                bN = ffma2(wn2[k2], hB2, bN);
            }

            // ---- ih parts (scalar, biases folded in) ----
            float ihrA = brj, ihzA = bzj, ihnA = binj;
            float ihrB = brj, ihzB = bzj, ihnB = binj;
#pragma unroll
            for (int f = 0; f < 6; f++) {
                ihrA = fmaf(ur[f], xa[f], ihrA);
                ihzA = fmaf(uz[f], xa[f], ihzA);
                ihnA = fmaf(un[f], xa[f], ihnA);
                ihrB = fmaf(ur[f], xb[f], ihrB);
                ihzB = fmaf(uz[f], xb[f], ihzB);
                ihnB = fmaf(un[f], xb[f], ihnB);
            }

            // ---- horizontal add + gates ----
            float2 v;
            v = up2(aR); float rA = sigm(v.x + v.y + ihrA);
            v = up2(aZ); float zA = sigm(v.x + v.y + ihzA);
            v = up2(aN); float nhA = v.x + v.y + bhnj;
            float nA = tanh_fast(fmaf(rA, nhA, ihnA));
            hAj = nA + zA * (hAj - nA);

            v = up2(bR); float rB = sigm(v.x + v.y + ihrB);
            v = up2(bZ); float zB = sigm(v.x + v.y + ihzB);
            v = up2(bN); float nhB = v.x + v.y + bhnj;
            float nB = tanh_fast(fmaf(rB, nhB, ihnB));
            hBj = nB + zB * (hBj - nB);

            // ---- re-gather packed pairs for next step's broadcasts ----
            float g0A = __shfl_sync(FULL, hAj, srcg);
            float g1A = __shfl_sync(FULL, hAj, srcg + 1);
            float g0B = __shfl_sync(FULL, hBj, srcg);
            float g1B = __shfl_sync(FULL, hBj, srcg + 1);
            hp0 = (j < 16) ? g0A : g0B;
            hp1 = (j < 16) ? g1A : g1B;
        }

        float vA = hAj, vB = hBj;
        g_A[(size_t)nodeA * HH + j] = vA > 0.f ? vA : 0.01f * vA;
        g_A[(size_t)nodeB * HH + j] = vB > 0.f ? vB : 0.01f * vB;
    }
}

// ---------------- hypergraph kernels ----------------
__device__ __forceinline__ void red_add_v2(float* p, float a, float b) {
    asm volatile("red.global.add.v2.f32 [%0], {%1, %2};"
                 :: "l"(p), "f"(a), "f"(b) : "memory");
}
__global__ void zero_deg_kernel() {
    int i = blockIdx.x * blockDim.x + threadIdx.x;
    if (i < NE) g_degB[i] = 0.f;
    if (i < NN) g_degD[i] = 0.f;
}
__global__ void count_deg_kernel(const int* __restrict__ nidx, const int* __restrict__ eidx) {
    int i = blockIdx.x * blockDim.x + threadIdx.x;
    if (i < NI) {
        atomicAdd(&g_degB[eidx[i]], 1.f);
        atomicAdd(&g_degD[nidx[i]], 1.f);
    }
}
__global__ void invert_deg_kernel() {
    int i = blockIdx.x * blockDim.x + threadIdx.x;
    if (i < NE) { float v = g_degB[i]; g_degB[i] = v > 0.f ? 1.f / v : 0.f; }
    if (i < NN) { float v = g_degD[i]; g_degD[i] = v > 0.f ? 1.f / v : 0.f; }
}
__global__ void zero_ef_agg_kernel() {
    int i = blockIdx.x * blockDim.x + threadIdx.x;
    if (i < NE * HH) g_EF[i] = 0.f;
    if (i < NN * HH) g_AGG[i] = 0.f;
}
__global__ void scatter_edge_kernel(const int* __restrict__ nidx, const int* __restrict__ eidx) {
    int idx = blockIdx.x * blockDim.x + threadIdx.x;
    if (idx < NI * 16) {
        int i = idx >> 4, c = (idx & 15) * 2;
        const float2 v = *reinterpret_cast<const float2*>(&g_XW[(size_t)nidx[i] * HH + c]);
        red_add_v2(&g_EF[eidx[i] * HH + c], v.x, v.y);
    }
}
__global__ void scatter_node_kernel(const int* __restrict__ nidx, const int* __restrict__ eidx) {
    int idx = blockIdx.x * blockDim.x + threadIdx.x;
    if (idx < NI * 16) {
        int i = idx >> 4, c = (idx & 15) * 2;
        int e = eidx[i];
        float s = g_degB[e];
        const float2 v = *reinterpret_cast<const float2*>(&g_EF[e * HH + c]);
        red_add_v2(&g_AGG[(size_t)nidx[i] * HH + c], v.x * s, v.y * s);
    }
}
__global__ void finalize_kernel(const float* __restrict__ bias) {
    int idx = blockIdx.x * blockDim.x + threadIdx.x;
    if (idx < NN * HH) {
        int n = idx >> 5, c = idx & 31;
        float v = g_AGG[idx] * g_degD[n] + bias[c];
        g_A[idx] = v > 0.f ? v : 0.2f * v;
    }
}
__global__ void dense_kernel(const float* __restrict__ W, const float* __restrict__ bias,
                             float* __restrict__ extout,
                             int nout, int hasBias, int hasAct, float slope) {
    __shared__ float sW[32 * 32];
    for (int i = threadIdx.x; i < nout * 32; i += blockDim.x) sW[i] = W[i];
    __syncthreads();
    int n = blockIdx.x * blockDim.x + threadIdx.x;
    if (n >= NN) return;
    float xin[32];
#pragma unroll
    for (int k = 0; k < 32; k++) xin[k] = g_A[(size_t)n * 32 + k];
    float* o = extout ? extout : g_XW;
    for (int j = 0; j < nout; j++) {
        float acc = hasBias ? bias[j] : 0.f;
#pragma unroll
        for (int k = 0; k < 32; k++) acc = fmaf(xin[k], sW[j * 32 + k], acc);
        if (hasAct) acc = acc > 0.f ? acc : slope * acc;
        o[(size_t)n * nout + j] = acc;
    }
}

// ---------------- launch ----------------
// gru_warp_kernel placed at launch #4 (the slot the profiler captures).
extern "C" void kernel_launch(void* const* d_in, const int* in_sizes, int n_in,
                              void* d_out, int out_size) {
    const float* price = (const float*)d_in[0];
    const float* W_ih = (const float*)d_in[2];
    const float* W_hh = (const float*)d_in[3];
    const float* b_ih = (const float*)d_in[4];
    const float* b_hh = (const float*)d_in[5];
    const float* W1   = (const float*)d_in[6];
    const float* b1   = (const float*)d_in[7];
    const float* W2   = (const float*)d_in[8];
    const float* b2   = (const float*)d_in[9];
    const float* Wl   = (const float*)d_in[10];
    const float* bl   = (const float*)d_in[11];
    const int*   nidx = (const int*)d_in[12];
    const int*   eidx = (const int*)d_in[13];
    float* out = (float*)d_out;

    const int B256 = 256;
    zero_deg_kernel<<<(NN + B256 - 1) / B256, B256>>>();                  // 1
    count_deg_kernel<<<(NI + B256 - 1) / B256, B256>>>(nidx, eidx);       // 2
    invert_deg_kernel<<<(NN + B256 - 1) / B256, B256>>>();                // 3
    gru_warp_kernel<<<1628, 32>>>(price, W_ih, W_hh, b_ih, b_hh);         // 4 <- profiled

    // conv1
    dense_kernel<<<(NN + 127) / 128, 128>>>(W1, nullptr, nullptr, 32, 0, 0, 0.f);
    zero_ef_agg_kernel<<<(NN * HH + B256 - 1) / B256, B256>>>();
    scatter_edge_kernel<<<(NI * 16 + B256 - 1) / B256, B256>>>(nidx, eidx);
    scatter_node_kernel<<<(NI * 16 + B256 - 1) / B256, B256>>>(nidx, eidx);
    finalize_kernel<<<(NN * HH + B256 - 1) / B256, B256>>>(b1);

    // conv2
    dense_kernel<<<(NN + 127) / 128, 128>>>(W2, nullptr, nullptr, 32, 0, 0, 0.f);
    zero_ef_agg_kernel<<<(NN * HH + B256 - 1) / B256, B256>>>();
    scatter_edge_kernel<<<(NI * 16 + B256 - 1) / B256, B256>>>(nidx, eidx);
    scatter_node_kernel<<<(NI * 16 + B256 - 1) / B256, B256>>>(nidx, eidx);
    finalize_kernel<<<(NN * HH + B256 - 1) / B256, B256>>>(b2);

    dense_kernel<<<(NN + 127) / 128, 128>>>(Wl, bl, out, RRF, 1, 1, 0.01f);
}